// round 1
// baseline (speedup 1.0000x reference)
#include <cuda_runtime.h>
#include <cstdint>
#include <cstddef>

// Problem constants (fixed by the reference)
#define NN    10000       // nodes
#define CC    256         // channels
#define KNBR  16          // neighbors
#define LDGG  10016       // padded leading dim of Gram scratch (40064 B rows, 128B aligned)
#define NBLD  1792        // 7 concatenated node-feature blocks of 256
#define EE    (NN*KNBR)   // 160000 edges

// NB column blocks (each 256 wide):
//  0: Qa = x@Wq_top   (gathered at src j)
//  1: Qb = x@Wq_bot   (at dst i)
//  2: Ka = x@Wk_top   (at j)
//  3: Kb = x@Wk_bot   (at i)
//  4: P  = x@W1_top   (at i;  m = [x_i, x_j])
//  5: R  = x@W1_bot   (at j)
//  6: S  = x@W_lin2   (at i;  residual path through lin2)

static __device__ float g_G[(size_t)NN * LDGG];     // Gram scratch (~401 MB)
static __device__ float g_NB[(size_t)NN * NBLD];    // node features (~72 MB)
static __device__ float g_Wcat[256 * NBLD];         // concatenated weights
static __device__ float g_n2[NN];                   // squared norms
static __device__ int   g_nbr[EE];                  // kNN indices
static __device__ float g_T[(size_t)EE * 256];      // relu(P_i + R_j + b1)
static __device__ float g_U[(size_t)EE * 256];      // T @ W_lin2

// ---------------------------------------------------------------------------
// Build Wcat[k][b*256+c] from the four weight inputs
// ---------------------------------------------------------------------------
__global__ void build_wcat_kernel(const float* __restrict__ Wq,
                                  const float* __restrict__ Wk,
                                  const float* __restrict__ W1,
                                  const float* __restrict__ W2) {
    int idx = blockIdx.x * 256 + threadIdx.x;       // 0 .. 256*1792-1
    int kk  = idx / NBLD;
    int n   = idx - kk * NBLD;
    int b   = n >> 8;
    int c   = n & 255;
    float v;
    switch (b) {
        case 0: v = Wq[(size_t)kk * 256 + c];         break;
        case 1: v = Wq[(size_t)(kk + 256) * 256 + c]; break;
        case 2: v = Wk[(size_t)kk * 256 + c];         break;
        case 3: v = Wk[(size_t)(kk + 256) * 256 + c]; break;
        case 4: v = W1[(size_t)kk * 256 + c];         break;
        case 5: v = W1[(size_t)(kk + 256) * 256 + c]; break;
        default: v = W2[(size_t)kk * 256 + c];        break;
    }
    g_Wcat[(size_t)kk * NBLD + n] = v;
}

// ---------------------------------------------------------------------------
// Row squared norms (1 warp per row)
// ---------------------------------------------------------------------------
__global__ void norms_kernel(const float* __restrict__ x) {
    int row  = blockIdx.x * 8 + (threadIdx.x >> 5);
    int lane = threadIdx.x & 31;
    const float4* xr = (const float4*)(x + (size_t)row * 256);
    float s = 0.f;
    #pragma unroll
    for (int r = 0; r < 2; r++) {
        float4 v = xr[lane + 32 * r];
        s += v.x * v.x + v.y * v.y + v.z * v.z + v.w * v.w;
    }
    #pragma unroll
    for (int o = 16; o; o >>= 1) s += __shfl_xor_sync(0xffffffffu, s, o);
    if (lane == 0) g_n2[row] = s;
}

// ---------------------------------------------------------------------------
// Generic fp32 SGEMM body: C[M,N] = A[M,256] @ B[256,N], row-major.
// BM=BN=128, BK=8, 256 threads, 8x8 per thread.
// ---------------------------------------------------------------------------
__device__ __forceinline__ void sgemm_body(const float* __restrict__ A, int lda,
                                           const float* __restrict__ B, int ldb,
                                           float* __restrict__ C, int ldc, int M) {
    __shared__ float As[8][128];
    __shared__ float Bs[8][128];

    int m0 = blockIdx.y * 128;
    int n0 = blockIdx.x * 128;
    int t  = threadIdx.x;

    int ar = t >> 1;            // 0..127
    int ac = (t & 1) * 4;       // 0 or 4
    int br = t >> 5;            // 0..7
    int bc = (t & 31) * 4;      // 0..124
    int tm = (t >> 4) * 8;
    int tn = (t & 15) * 8;

    float acc[8][8];
    #pragma unroll
    for (int i = 0; i < 8; i++)
        #pragma unroll
        for (int j = 0; j < 8; j++) acc[i][j] = 0.f;

    bool aval = (m0 + ar) < M;
    const float* Ap = A + (size_t)(m0 + ar) * lda + ac;
    const float* Bp = B + (size_t)br * ldb + n0 + bc;

    for (int k0 = 0; k0 < 256; k0 += 8) {
        float4 av = aval ? *(const float4*)(Ap + k0) : make_float4(0.f, 0.f, 0.f, 0.f);
        As[ac + 0][ar] = av.x;
        As[ac + 1][ar] = av.y;
        As[ac + 2][ar] = av.z;
        As[ac + 3][ar] = av.w;
        *(float4*)&Bs[br][bc] = *(const float4*)(Bp + (size_t)k0 * ldb);
        __syncthreads();
        #pragma unroll
        for (int kk = 0; kk < 8; kk++) {
            float a[8], b[8];
            *(float4*)(a + 0) = *(const float4*)&As[kk][tm];
            *(float4*)(a + 4) = *(const float4*)&As[kk][tm + 4];
            *(float4*)(b + 0) = *(const float4*)&Bs[kk][tn];
            *(float4*)(b + 4) = *(const float4*)&Bs[kk][tn + 4];
            #pragma unroll
            for (int i = 0; i < 8; i++)
                #pragma unroll
                for (int j = 0; j < 8; j++)
                    acc[i][j] = fmaf(a[i], b[j], acc[i][j]);
        }
        __syncthreads();
    }

    if (m0 + 128 <= M) {
        #pragma unroll
        for (int i = 0; i < 8; i++) {
            float* Cp = C + (size_t)(m0 + tm + i) * ldc + n0 + tn;
            *(float4*)(Cp + 0) = make_float4(acc[i][0], acc[i][1], acc[i][2], acc[i][3]);
            *(float4*)(Cp + 4) = make_float4(acc[i][4], acc[i][5], acc[i][6], acc[i][7]);
        }
    } else {
        #pragma unroll
        for (int i = 0; i < 8; i++) {
            int m = m0 + tm + i;
            if (m < M) {
                float* Cp = C + (size_t)m * ldc + n0 + tn;
                #pragma unroll
                for (int j = 0; j < 8; j++) Cp[j] = acc[i][j];
            }
        }
    }
}

// Node GEMM: x[10000,256] @ Wcat[256,1792] -> g_NB
__global__ void sgemm_node_kernel(const float* __restrict__ x) {
    sgemm_body(x, 256, g_Wcat, NBLD, g_NB, NBLD, NN);
}

// Edge GEMM: g_T[160000,256] @ W_lin2[256,256] -> g_U
__global__ void sgemm_edge_kernel(const float* __restrict__ W2) {
    sgemm_body(g_T, 256, W2, 256, g_U, 256, EE);
}

// ---------------------------------------------------------------------------
// Gram: G = x @ x^T, upper-triangular tiles only, mirrored on store.
// ---------------------------------------------------------------------------
__global__ void gram_kernel(const float* __restrict__ x) {
    int bi = blockIdx.y;   // row tile
    int bj = blockIdx.x;   // col tile
    if (bj < bi) return;

    __shared__ float As[8][128];
    __shared__ float Bs[8][128];

    int m0 = bi * 128;
    int n0 = bj * 128;
    int t  = threadIdx.x;
    int r  = t >> 1;
    int c4 = (t & 1) * 4;
    int tm = (t >> 4) * 8;
    int tn = (t & 15) * 8;

    float acc[8][8];
    #pragma unroll
    for (int i = 0; i < 8; i++)
        #pragma unroll
        for (int j = 0; j < 8; j++) acc[i][j] = 0.f;

    bool avalid = (m0 + r) < NN;
    bool bvalid = (n0 + r) < NN;
    const float* Ap = x + (size_t)(m0 + r) * 256 + c4;
    const float* Bp = x + (size_t)(n0 + r) * 256 + c4;

    for (int k0 = 0; k0 < 256; k0 += 8) {
        float4 av = avalid ? *(const float4*)(Ap + k0) : make_float4(0.f, 0.f, 0.f, 0.f);
        float4 bv = bvalid ? *(const float4*)(Bp + k0) : make_float4(0.f, 0.f, 0.f, 0.f);
        As[c4 + 0][r] = av.x; As[c4 + 1][r] = av.y; As[c4 + 2][r] = av.z; As[c4 + 3][r] = av.w;
        Bs[c4 + 0][r] = bv.x; Bs[c4 + 1][r] = bv.y; Bs[c4 + 2][r] = bv.z; Bs[c4 + 3][r] = bv.w;
        __syncthreads();
        #pragma unroll
        for (int kk = 0; kk < 8; kk++) {
            float a[8], b[8];
            *(float4*)(a + 0) = *(const float4*)&As[kk][tm];
            *(float4*)(a + 4) = *(const float4*)&As[kk][tm + 4];
            *(float4*)(b + 0) = *(const float4*)&Bs[kk][tn];
            *(float4*)(b + 4) = *(const float4*)&Bs[kk][tn + 4];
            #pragma unroll
            for (int i = 0; i < 8; i++)
                #pragma unroll
                for (int j = 0; j < 8; j++)
                    acc[i][j] = fmaf(a[i], b[j], acc[i][j]);
        }
        __syncthreads();
    }

    bool full = (m0 + 128 <= NN) && (n0 + 128 <= NN);
    if (full) {
        #pragma unroll
        for (int i = 0; i < 8; i++) {
            float* Gp = g_G + (size_t)(m0 + tm + i) * LDGG + n0 + tn;
            *(float4*)(Gp + 0) = make_float4(acc[i][0], acc[i][1], acc[i][2], acc[i][3]);
            *(float4*)(Gp + 4) = make_float4(acc[i][4], acc[i][5], acc[i][6], acc[i][7]);
        }
        if (bi != bj) {
            #pragma unroll
            for (int j = 0; j < 8; j++) {
                float* Gp = g_G + (size_t)(n0 + tn + j) * LDGG + m0 + tm;
                *(float4*)(Gp + 0) = make_float4(acc[0][j], acc[1][j], acc[2][j], acc[3][j]);
                *(float4*)(Gp + 4) = make_float4(acc[4][j], acc[5][j], acc[6][j], acc[7][j]);
            }
        }
    } else {
        #pragma unroll
        for (int i = 0; i < 8; i++) {
            int m = m0 + tm + i;
            if (m < NN) {
                #pragma unroll
                for (int j = 0; j < 8; j++) {
                    int n = n0 + tn + j;
                    if (n < NN) g_G[(size_t)m * LDGG + n] = acc[i][j];
                }
            }
        }
        if (bi != bj) {
            #pragma unroll
            for (int j = 0; j < 8; j++) {
                int n = n0 + tn + j;
                if (n < NN) {
                    #pragma unroll
                    for (int i = 0; i < 8; i++) {
                        int m = m0 + tm + i;
                        if (m < NN) g_G[(size_t)n * LDGG + m] = acc[i][j];
                    }
                }
            }
        }
    }
}

// ---------------------------------------------------------------------------
// Top-16 nearest per row (1 warp per row; per-lane running top-16 + merge)
// ---------------------------------------------------------------------------
__global__ void topk_kernel() {
    __shared__ float sd[8][512];
    __shared__ int   si[8][512];

    int w    = threadIdx.x >> 5;
    int lane = threadIdx.x & 31;
    int row  = blockIdx.x * 8 + w;

    const float FINF = __int_as_float(0x7f800000);
    float n2i = g_n2[row];
    const float* Gr = g_G + (size_t)row * LDGG;

    float best[16];
    int   bid[16];
    #pragma unroll
    for (int q = 0; q < 16; q++) { best[q] = FINF; bid[q] = -1; }
    float worst = FINF;

    for (int j = lane; j < NN; j += 32) {
        float d = n2i + g_n2[j] - 2.f * Gr[j];
        if (j == row) d = FINF;
        if (d < worst) {
            float mx = best[0]; int am = 0;
            #pragma unroll
            for (int q = 1; q < 16; q++) if (best[q] > mx) { mx = best[q]; am = q; }
            #pragma unroll
            for (int q = 0; q < 16; q++) if (q == am) { best[q] = d; bid[q] = j; }
            worst = best[0];
            #pragma unroll
            for (int q = 1; q < 16; q++) worst = fmaxf(worst, best[q]);
        }
    }

    #pragma unroll
    for (int q = 0; q < 16; q++) {
        sd[w][lane * 16 + q] = best[q];
        si[w][lane * 16 + q] = bid[q];
    }
    __syncwarp();

    for (int sel = 0; sel < 16; sel++) {
        float m = FINF; int mp = 0;
        #pragma unroll
        for (int r2 = 0; r2 < 16; r2++) {
            int p = lane + 32 * r2;
            float v = sd[w][p];
            if (v < m) { m = v; mp = p; }
        }
        #pragma unroll
        for (int o = 16; o; o >>= 1) {
            float om = __shfl_xor_sync(0xffffffffu, m, o);
            int   op = __shfl_xor_sync(0xffffffffu, mp, o);
            if (om < m) { m = om; mp = op; }
        }
        if (lane == 0) {
            g_nbr[row * 16 + sel] = si[w][mp];
            sd[w][mp] = FINF;
        }
        __syncwarp();
    }
}

// ---------------------------------------------------------------------------
// T[e][c] = relu(P[i][c] + R[j][c] + b1[c]),  e = i*16 + kk, j = nbr[e]
// ---------------------------------------------------------------------------
__global__ void build_T_kernel(const float* __restrict__ b1) {
    size_t idx = (size_t)blockIdx.x * 256 + threadIdx.x;   // over EE*64 float4s
    int e  = (int)(idx >> 6);
    int c4 = (int)(idx & 63) << 2;
    int i  = e >> 4;
    int j  = g_nbr[e];
    float4 p  = *(const float4*)&g_NB[(size_t)i * NBLD + 1024 + c4];
    float4 rr = *(const float4*)&g_NB[(size_t)j * NBLD + 1280 + c4];
    float4 bb = *(const float4*)&b1[c4];
    float4 o;
    o.x = fmaxf(p.x + rr.x + bb.x, 0.f);
    o.y = fmaxf(p.y + rr.y + bb.y, 0.f);
    o.z = fmaxf(p.z + rr.z + bb.z, 0.f);
    o.w = fmaxf(p.w + rr.w + bb.w, 0.f);
    *(float4*)&g_T[(size_t)e * 256 + c4] = o;
}

// ---------------------------------------------------------------------------
// Combine: per node i, compute ew per edge, mix with h2 = U + S_i + b2,
// mean-aggregate 16 messages. 128 threads per node (thread t owns s = t).
// ---------------------------------------------------------------------------
__global__ void combine_kernel(const float* __restrict__ bq,
                               const float* __restrict__ bk,
                               const float* __restrict__ b2,
                               float* __restrict__ out) {
    int i = blockIdx.x;
    int t = threadIdx.x;         // 0..127
    __shared__ float qb[256], kb[256], sb[256], ewsh[4];

    const float* nbi = g_NB + (size_t)i * NBLD;
    for (int c = t; c < 256; c += 128) {
        qb[c] = nbi[256 + c] + bq[c];     // Qb_i + b_q
        kb[c] = nbi[768 + c] + bk[c];     // Kb_i + b_k
        sb[c] = nbi[1536 + c] + b2[c];    // S_i + b_lin2
    }
    __syncthreads();

    int w    = t >> 5;           // warp 0..3 -> (h,g) = (w>>1, w&1)
    int lane = t & 31;
    int h = w >> 1, g = w & 1;

    float a0 = 0.f, a1 = 0.f;

    for (int kk = 0; kk < 16; kk++) {
        int e = i * 16 + kk;
        int j = g_nbr[e];
        const float* qaj = g_NB + (size_t)j * NBLD;        // Qa
        const float* kaj = qaj + 512;                      // Ka
        float s = 0.f;
        #pragma unroll
        for (int r = 0; r < 4; r++) {
            int d = lane + 32 * r;
            float qv = qaj[h * 128 + d] + qb[h * 128 + d];
            float kv = kaj[g * 128 + d] + kb[g * 128 + d];
            s = fmaf(qv, kv, s);
        }
        #pragma unroll
        for (int o = 16; o; o >>= 1) s += __shfl_xor_sync(0xffffffffu, s, o);
        if (lane == 0) ewsh[w] = s * 0.0625f;              // * 1/sqrt(256)
        __syncthreads();
        float e00 = ewsh[0], e01 = ewsh[1], e10 = ewsh[2], e11 = ewsh[3];
        float2 u2 = *(const float2*)&g_U[(size_t)e * 256 + 2 * t];
        float u0 = u2.x + sb[2 * t];
        float u1 = u2.y + sb[2 * t + 1];
        a0 += u0 * e00 + u1 * e10;
        a1 += u0 * e01 + u1 * e11;
        __syncthreads();
    }

    out[(size_t)i * 256 + 2 * t]     = a0 * 0.0625f;       // mean over 16 edges
    out[(size_t)i * 256 + 2 * t + 1] = a1 * 0.0625f;
}

// ---------------------------------------------------------------------------
// Launch
// ---------------------------------------------------------------------------
extern "C" void kernel_launch(void* const* d_in, const int* in_sizes, int n_in,
                              void* d_out, int out_size) {
    const float* x  = (const float*)d_in[0];
    const float* W1 = (const float*)d_in[1];
    const float* b1 = (const float*)d_in[2];
    const float* W2 = (const float*)d_in[3];
    const float* b2 = (const float*)d_in[4];
    const float* Wq = (const float*)d_in[5];
    const float* bq = (const float*)d_in[6];
    const float* Wk = (const float*)d_in[7];
    const float* bk = (const float*)d_in[8];
    float* out = (float*)d_out;

    build_wcat_kernel<<<1792, 256>>>(Wq, Wk, W1, W2);
    norms_kernel<<<1250, 256>>>(x);
    sgemm_node_kernel<<<dim3(NBLD / 128, (NN + 127) / 128), 256>>>(x);
    gram_kernel<<<dim3((NN + 127) / 128, (NN + 127) / 128), 256>>>(x);
    topk_kernel<<<1250, 256>>>();
    build_T_kernel<<<EE * 64 / 256, 256>>>(b1);
    sgemm_edge_kernel<<<dim3(2, EE / 128), 256>>>(W2);
    combine_kernel<<<NN, 128>>>(bq, bk, b2, out);
}

// round 2
// speedup vs baseline: 1.0346x; 1.0346x over previous
#include <cuda_runtime.h>
#include <cstdint>
#include <cstddef>

// Problem constants (fixed by the reference)
#define NN    10000       // nodes
#define CC    256         // channels
#define KNBR  16          // neighbors
#define LDGG  10016       // padded leading dim of Gram scratch
#define NBLD  1792        // 7 concatenated node-feature blocks of 256
#define EE    (NN*KNBR)   // 160000 edges

// NB column blocks (each 256 wide), biases folded in epilogue:
//  0: Qa = x@Wq_top            (gathered at src j)
//  1: Qb = x@Wq_bot + b_q      (at dst i)
//  2: Ka = x@Wk_top            (at j)
//  3: Kb = x@Wk_bot + b_k      (at i)
//  4: P  = x@W1_top + b_lin1   (at i;  m = [x_i, x_j])
//  5: R  = x@W1_bot            (at j)
//  6: S  = x@W_lin2 + b_lin2   (at i; residual path through lin2)

static __device__ float g_G[(size_t)NN * LDGG];     // Gram scratch (~401 MB)
static __device__ float g_NB[(size_t)NN * NBLD];    // node features (~72 MB)
static __device__ float g_Wcat[256 * NBLD];         // concatenated weights
static __device__ float g_bias[NBLD];               // concatenated biases
static __device__ float g_n2[NN];                   // squared norms
static __device__ int   g_nbr[EE];                  // kNN indices
static __device__ float g_U[(size_t)EE * 256];      // relu(P_i+R_j) @ W_lin2

typedef unsigned long long u64;

// ---------------------------------------------------------------------------
// Packed f32x2 helpers (sm_100+)
// ---------------------------------------------------------------------------
__device__ __forceinline__ u64 splat2(float v) {
    u64 r; asm("mov.b64 %0, {%1, %1};" : "=l"(r) : "f"(v)); return r;
}
__device__ __forceinline__ void fma2(u64& d, u64 a, u64 b) {
    asm("fma.rn.f32x2 %0, %1, %2, %0;" : "+l"(d) : "l"(a), "l"(b));
}
__device__ __forceinline__ void add2(u64& d, u64 a) {
    asm("add.rn.f32x2 %0, %0, %1;" : "+l"(d) : "l"(a));
}
__device__ __forceinline__ float2 unpack2(u64 v) {
    float2 f; asm("mov.b64 {%0, %1}, %2;" : "=f"(f.x), "=f"(f.y) : "l"(v)); return f;
}

// Shared-tile MMA micro-kernel: 8x8 per thread, packed along N (4 x f32x2).
__device__ __forceinline__ void mma_tile(const float (*As)[128], const float (*Bs)[128],
                                         int tm, int tn, u64 acc2[8][4]) {
    #pragma unroll
    for (int kk = 0; kk < 8; kk++) {
        float a[8];
        *(float4*)(a + 0) = *(const float4*)&As[kk][tm];
        *(float4*)(a + 4) = *(const float4*)&As[kk][tm + 4];
        ulonglong2 b01 = *(const ulonglong2*)&Bs[kk][tn];
        ulonglong2 b23 = *(const ulonglong2*)&Bs[kk][tn + 4];
        u64 bp[4] = {b01.x, b01.y, b23.x, b23.y};
        #pragma unroll
        for (int i = 0; i < 8; i++) {
            u64 ai = splat2(a[i]);
            #pragma unroll
            for (int p = 0; p < 4; p++) fma2(acc2[i][p], ai, bp[p]);
        }
    }
}

// ---------------------------------------------------------------------------
// Build Wcat and bias concat
// ---------------------------------------------------------------------------
__global__ void build_wcat_kernel(const float* __restrict__ Wq,
                                  const float* __restrict__ Wk,
                                  const float* __restrict__ W1,
                                  const float* __restrict__ W2) {
    int idx = blockIdx.x * 256 + threadIdx.x;
    int kk  = idx / NBLD;
    int n   = idx - kk * NBLD;
    int b   = n >> 8;
    int c   = n & 255;
    float v;
    switch (b) {
        case 0: v = Wq[(size_t)kk * 256 + c];         break;
        case 1: v = Wq[(size_t)(kk + 256) * 256 + c]; break;
        case 2: v = Wk[(size_t)kk * 256 + c];         break;
        case 3: v = Wk[(size_t)(kk + 256) * 256 + c]; break;
        case 4: v = W1[(size_t)kk * 256 + c];         break;
        case 5: v = W1[(size_t)(kk + 256) * 256 + c]; break;
        default: v = W2[(size_t)kk * 256 + c];        break;
    }
    g_Wcat[(size_t)kk * NBLD + n] = v;
}

__global__ void build_bias_kernel(const float* __restrict__ bq,
                                  const float* __restrict__ bk,
                                  const float* __restrict__ b1,
                                  const float* __restrict__ b2) {
    int n = blockIdx.x * 256 + threadIdx.x;   // 0..1791
    int b = n >> 8, c = n & 255;
    float v = 0.f;
    if (b == 1) v = bq[c];
    else if (b == 3) v = bk[c];
    else if (b == 4) v = b1[c];
    else if (b == 6) v = b2[c];
    g_bias[n] = v;
}

// ---------------------------------------------------------------------------
// Row squared norms (1 warp per row)
// ---------------------------------------------------------------------------
__global__ void norms_kernel(const float* __restrict__ x) {
    int row  = blockIdx.x * 8 + (threadIdx.x >> 5);
    int lane = threadIdx.x & 31;
    const float4* xr = (const float4*)(x + (size_t)row * 256);
    float s = 0.f;
    #pragma unroll
    for (int r = 0; r < 2; r++) {
        float4 v = xr[lane + 32 * r];
        s += v.x * v.x + v.y * v.y + v.z * v.z + v.w * v.w;
    }
    #pragma unroll
    for (int o = 16; o; o >>= 1) s += __shfl_xor_sync(0xffffffffu, s, o);
    if (lane == 0) g_n2[row] = s;
}

// ---------------------------------------------------------------------------
// Node GEMM: x[10000,256] @ Wcat[256,1792] + bias -> g_NB  (f32x2)
// ---------------------------------------------------------------------------
__global__ void sgemm_node_kernel(const float* __restrict__ x) {
    __shared__ __align__(16) float As[8][128];
    __shared__ __align__(16) float Bs[8][128];

    int m0 = blockIdx.y * 128;
    int n0 = blockIdx.x * 128;
    int t  = threadIdx.x;
    int ar = t >> 1, ac = (t & 1) * 4;
    int br = t >> 5, bc = (t & 31) * 4;
    int tm = (t >> 4) * 8, tn = (t & 15) * 8;

    u64 acc2[8][4];
    #pragma unroll
    for (int i = 0; i < 8; i++)
        #pragma unroll
        for (int p = 0; p < 4; p++) acc2[i][p] = 0ull;

    bool aval = (m0 + ar) < NN;
    const float* Ap = x + (size_t)(m0 + ar) * 256 + ac;
    const float* Bp = g_Wcat + (size_t)br * NBLD + n0 + bc;

    for (int k0 = 0; k0 < 256; k0 += 8) {
        float4 av = aval ? *(const float4*)(Ap + k0) : make_float4(0.f, 0.f, 0.f, 0.f);
        As[ac + 0][ar] = av.x; As[ac + 1][ar] = av.y;
        As[ac + 2][ar] = av.z; As[ac + 3][ar] = av.w;
        *(float4*)&Bs[br][bc] = *(const float4*)(Bp + (size_t)k0 * NBLD);
        __syncthreads();
        mma_tile(As, Bs, tm, tn, acc2);
        __syncthreads();
    }

    // bias add (packed)
    const u64* bias2 = (const u64*)(g_bias + n0 + tn);
    u64 bv[4] = {bias2[0], bias2[1], bias2[2], bias2[3]};
    #pragma unroll
    for (int i = 0; i < 8; i++)
        #pragma unroll
        for (int p = 0; p < 4; p++) add2(acc2[i][p], bv[p]);

    #pragma unroll
    for (int i = 0; i < 8; i++) {
        int m = m0 + tm + i;
        if (m < NN) {
            u64* Cp = (u64*)(g_NB + (size_t)m * NBLD + n0 + tn);
            ((ulonglong2*)Cp)[0] = make_ulonglong2(acc2[i][0], acc2[i][1]);
            ((ulonglong2*)Cp)[1] = make_ulonglong2(acc2[i][2], acc2[i][3]);
        }
    }
}

// ---------------------------------------------------------------------------
// Gram: G = x @ x^T, upper tiles only, mirrored on store (f32x2)
// ---------------------------------------------------------------------------
__global__ void gram_kernel(const float* __restrict__ x) {
    int bi = blockIdx.y, bj = blockIdx.x;
    if (bj < bi) return;

    __shared__ __align__(16) float As[8][128];
    __shared__ __align__(16) float Bs[8][128];

    int m0 = bi * 128, n0 = bj * 128;
    int t  = threadIdx.x;
    int r  = t >> 1, c4 = (t & 1) * 4;
    int tm = (t >> 4) * 8, tn = (t & 15) * 8;

    u64 acc2[8][4];
    #pragma unroll
    for (int i = 0; i < 8; i++)
        #pragma unroll
        for (int p = 0; p < 4; p++) acc2[i][p] = 0ull;

    bool avalid = (m0 + r) < NN;
    bool bvalid = (n0 + r) < NN;
    const float* Ap = x + (size_t)(m0 + r) * 256 + c4;
    const float* Bp = x + (size_t)(n0 + r) * 256 + c4;

    for (int k0 = 0; k0 < 256; k0 += 8) {
        float4 av = avalid ? *(const float4*)(Ap + k0) : make_float4(0.f, 0.f, 0.f, 0.f);
        float4 bv = bvalid ? *(const float4*)(Bp + k0) : make_float4(0.f, 0.f, 0.f, 0.f);
        As[c4 + 0][r] = av.x; As[c4 + 1][r] = av.y; As[c4 + 2][r] = av.z; As[c4 + 3][r] = av.w;
        Bs[c4 + 0][r] = bv.x; Bs[c4 + 1][r] = bv.y; Bs[c4 + 2][r] = bv.z; Bs[c4 + 3][r] = bv.w;
        __syncthreads();
        mma_tile(As, Bs, tm, tn, acc2);
        __syncthreads();
    }

    bool full = (m0 + 128 <= NN) && (n0 + 128 <= NN);
    if (full) {
        #pragma unroll
        for (int i = 0; i < 8; i++) {
            ulonglong2* Gp = (ulonglong2*)(g_G + (size_t)(m0 + tm + i) * LDGG + n0 + tn);
            Gp[0] = make_ulonglong2(acc2[i][0], acc2[i][1]);
            Gp[1] = make_ulonglong2(acc2[i][2], acc2[i][3]);
        }
        if (bi != bj) {
            float acc[8][8];
            #pragma unroll
            for (int i = 0; i < 8; i++)
                #pragma unroll
                for (int p = 0; p < 4; p++) {
                    float2 f = unpack2(acc2[i][p]);
                    acc[i][2 * p] = f.x; acc[i][2 * p + 1] = f.y;
                }
            #pragma unroll
            for (int j = 0; j < 8; j++) {
                float* Gp = g_G + (size_t)(n0 + tn + j) * LDGG + m0 + tm;
                *(float4*)(Gp + 0) = make_float4(acc[0][j], acc[1][j], acc[2][j], acc[3][j]);
                *(float4*)(Gp + 4) = make_float4(acc[4][j], acc[5][j], acc[6][j], acc[7][j]);
            }
        }
    } else {
        float acc[8][8];
        #pragma unroll
        for (int i = 0; i < 8; i++)
            #pragma unroll
            for (int p = 0; p < 4; p++) {
                float2 f = unpack2(acc2[i][p]);
                acc[i][2 * p] = f.x; acc[i][2 * p + 1] = f.y;
            }
        #pragma unroll
        for (int i = 0; i < 8; i++) {
            int m = m0 + tm + i;
            if (m < NN) {
                #pragma unroll
                for (int j = 0; j < 8; j++) {
                    int n = n0 + tn + j;
                    if (n < NN) g_G[(size_t)m * LDGG + n] = acc[i][j];
                }
            }
        }
        if (bi != bj) {
            #pragma unroll
            for (int j = 0; j < 8; j++) {
                int n = n0 + tn + j;
                if (n < NN) {
                    #pragma unroll
                    for (int i = 0; i < 8; i++) {
                        int m = m0 + tm + i;
                        if (m < NN) g_G[(size_t)n * LDGG + m] = acc[i][j];
                    }
                }
            }
        }
    }
}

// ---------------------------------------------------------------------------
// Top-16 nearest per row (1 warp per row)
// ---------------------------------------------------------------------------
__global__ void topk_kernel() {
    __shared__ float sd[8][512];
    __shared__ int   si[8][512];

    int w    = threadIdx.x >> 5;
    int lane = threadIdx.x & 31;
    int row  = blockIdx.x * 8 + w;

    const float FINF = __int_as_float(0x7f800000);
    float n2i = g_n2[row];
    const float* Gr = g_G + (size_t)row * LDGG;

    float best[16];
    int   bid[16];
    #pragma unroll
    for (int q = 0; q < 16; q++) { best[q] = FINF; bid[q] = -1; }
    float worst = FINF;

    for (int j = lane; j < NN; j += 32) {
        float d = n2i + g_n2[j] - 2.f * Gr[j];
        if (j == row) d = FINF;
        if (d < worst) {
            float mx = best[0]; int am = 0;
            #pragma unroll
            for (int q = 1; q < 16; q++) if (best[q] > mx) { mx = best[q]; am = q; }
            #pragma unroll
            for (int q = 0; q < 16; q++) if (q == am) { best[q] = d; bid[q] = j; }
            worst = best[0];
            #pragma unroll
            for (int q = 1; q < 16; q++) worst = fmaxf(worst, best[q]);
        }
    }

    #pragma unroll
    for (int q = 0; q < 16; q++) {
        sd[w][lane * 16 + q] = best[q];
        si[w][lane * 16 + q] = bid[q];
    }
    __syncwarp();

    for (int sel = 0; sel < 16; sel++) {
        float m = FINF; int mp = 0;
        #pragma unroll
        for (int r2 = 0; r2 < 16; r2++) {
            int p = lane + 32 * r2;
            float v = sd[w][p];
            if (v < m) { m = v; mp = p; }
        }
        #pragma unroll
        for (int o = 16; o; o >>= 1) {
            float om = __shfl_xor_sync(0xffffffffu, m, o);
            int   op = __shfl_xor_sync(0xffffffffu, mp, o);
            if (om < m) { m = om; mp = op; }
        }
        if (lane == 0) {
            g_nbr[row * 16 + sel] = si[w][mp];
            sd[w][mp] = FINF;
        }
        __syncwarp();
    }
}

// ---------------------------------------------------------------------------
// Edge GEMM, fused T: U[e] = relu(P_i + R_j) @ W2   (bias b1 folded into P)
// ---------------------------------------------------------------------------
__global__ void edge_gemm_fused_kernel(const float* __restrict__ W2) {
    __shared__ __align__(16) float As[8][128];
    __shared__ __align__(16) float Bs[8][128];

    int m0 = blockIdx.y * 128;
    int n0 = blockIdx.x * 128;
    int t  = threadIdx.x;
    int ar = t >> 1, ac = (t & 1) * 4;
    int br = t >> 5, bc = (t & 31) * 4;
    int tm = (t >> 4) * 8, tn = (t & 15) * 8;

    u64 acc2[8][4];
    #pragma unroll
    for (int i = 0; i < 8; i++)
        #pragma unroll
        for (int p = 0; p < 4; p++) acc2[i][p] = 0ull;

    int e = m0 + ar;                    // EE divisible by 128 -> always valid
    int i_node = e >> 4;
    int j_node = g_nbr[e];
    const float* Pp = g_NB + (size_t)i_node * NBLD + 1024 + ac;   // P block (+b1)
    const float* Rp = g_NB + (size_t)j_node * NBLD + 1280 + ac;   // R block
    const float* Bp = W2 + (size_t)br * 256 + n0 + bc;

    for (int k0 = 0; k0 < 256; k0 += 8) {
        float4 pv = *(const float4*)(Pp + k0);
        float4 rv = *(const float4*)(Rp + k0);
        As[ac + 0][ar] = fmaxf(pv.x + rv.x, 0.f);
        As[ac + 1][ar] = fmaxf(pv.y + rv.y, 0.f);
        As[ac + 2][ar] = fmaxf(pv.z + rv.z, 0.f);
        As[ac + 3][ar] = fmaxf(pv.w + rv.w, 0.f);
        *(float4*)&Bs[br][bc] = *(const float4*)(Bp + (size_t)k0 * 256);
        __syncthreads();
        mma_tile(As, Bs, tm, tn, acc2);
        __syncthreads();
    }

    #pragma unroll
    for (int i = 0; i < 8; i++) {
        ulonglong2* Cp = (ulonglong2*)(g_U + (size_t)(m0 + tm + i) * 256 + n0 + tn);
        Cp[0] = make_ulonglong2(acc2[i][0], acc2[i][1]);
        Cp[1] = make_ulonglong2(acc2[i][2], acc2[i][3]);
    }
}

// ---------------------------------------------------------------------------
// Combine: ew per edge + mixing + mean aggregation (biases already folded)
// ---------------------------------------------------------------------------
__global__ void combine_kernel(float* __restrict__ out) {
    int i = blockIdx.x;
    int t = threadIdx.x;         // 0..127
    __shared__ float qb[256], kb[256], sb[256], ewsh[4];

    const float* nbi = g_NB + (size_t)i * NBLD;
    for (int c = t; c < 256; c += 128) {
        qb[c] = nbi[256 + c];     // Qb_i (+b_q)
        kb[c] = nbi[768 + c];     // Kb_i (+b_k)
        sb[c] = nbi[1536 + c];    // S_i  (+b_lin2)
    }
    __syncthreads();

    int w    = t >> 5;           // warp 0..3 -> (h,g)
    int lane = t & 31;
    int h = w >> 1, g = w & 1;

    float a0 = 0.f, a1 = 0.f;

    for (int kk = 0; kk < 16; kk++) {
        int e = i * 16 + kk;
        int j = g_nbr[e];
        const float* qaj = g_NB + (size_t)j * NBLD;        // Qa
        const float* kaj = qaj + 512;                      // Ka
        float s = 0.f;
        #pragma unroll
        for (int r = 0; r < 4; r++) {
            int d = lane + 32 * r;
            float qv = qaj[h * 128 + d] + qb[h * 128 + d];
            float kv = kaj[g * 128 + d] + kb[g * 128 + d];
            s = fmaf(qv, kv, s);
        }
        #pragma unroll
        for (int o = 16; o; o >>= 1) s += __shfl_xor_sync(0xffffffffu, s, o);
        if (lane == 0) ewsh[w] = s * 0.0625f;              // * 1/sqrt(256)
        __syncthreads();
        float e00 = ewsh[0], e01 = ewsh[1], e10 = ewsh[2], e11 = ewsh[3];
        float2 u2 = *(const float2*)&g_U[(size_t)e * 256 + 2 * t];
        float u0 = u2.x + sb[2 * t];
        float u1 = u2.y + sb[2 * t + 1];
        a0 += u0 * e00 + u1 * e10;
        a1 += u0 * e01 + u1 * e11;
        __syncthreads();
    }

    out[(size_t)i * 256 + 2 * t]     = a0 * 0.0625f;       // mean over 16 edges
    out[(size_t)i * 256 + 2 * t + 1] = a1 * 0.0625f;
}

// ---------------------------------------------------------------------------
// Launch
// ---------------------------------------------------------------------------
extern "C" void kernel_launch(void* const* d_in, const int* in_sizes, int n_in,
                              void* d_out, int out_size) {
    const float* x  = (const float*)d_in[0];
    const float* W1 = (const float*)d_in[1];
    const float* b1 = (const float*)d_in[2];
    const float* W2 = (const float*)d_in[3];
    const float* b2 = (const float*)d_in[4];
    const float* Wq = (const float*)d_in[5];
    const float* bq = (const float*)d_in[6];
    const float* Wk = (const float*)d_in[7];
    const float* bk = (const float*)d_in[8];
    float* out = (float*)d_out;

    build_wcat_kernel<<<1792, 256>>>(Wq, Wk, W1, W2);
    build_bias_kernel<<<7, 256>>>(bq, bk, b1, b2);
    norms_kernel<<<1250, 256>>>(x);
    sgemm_node_kernel<<<dim3(NBLD / 128, (NN + 127) / 128), 256>>>(x);
    gram_kernel<<<dim3((NN + 127) / 128, (NN + 127) / 128), 256>>>(x);
    topk_kernel<<<1250, 256>>>();
    edge_gemm_fused_kernel<<<dim3(2, EE / 128), 256>>>(W2);
    combine_kernel<<<NN, 128>>>(out);
}

// round 5
// speedup vs baseline: 1.1066x; 1.0696x over previous
#include <cuda_runtime.h>
#include <cstdint>
#include <cstddef>

#define NN    10000
#define KNBR  16
#define LDGG  10016
#define NBLD  1792
#define EE    (NN*KNBR)

// NB column blocks (256 each): 0:Qa 1:Qb(+bq) 2:Ka 3:Kb(+bk) 4:P(+b1) 5:R 6:S(+b2)
static __device__ float g_G[(size_t)NN * LDGG];     // Gram scratch
static __device__ float g_NB[(size_t)NN * NBLD];    // node features
static __device__ float g_WT[(size_t)NBLD * 256];   // Wcat^T  [n][k]
static __device__ float g_bias[NBLD];
static __device__ float g_n2[NN];
static __device__ int   g_nbr[EE];
static __device__ float g_U[(size_t)EE * 256];      // relu(P_i+R_j) @ W2

// ---------------------------------------------------------------------------
// tf32 mma.sync helpers (arch-agnostic PTX, works on plain sm_100 target)
// ---------------------------------------------------------------------------
__device__ __forceinline__ uint32_t f2tf(float v) {
    uint32_t u; asm("cvt.rna.tf32.f32 %0, %1;" : "=r"(u) : "f"(v)); return u;
}
__device__ __forceinline__ void split_tf(float v, uint32_t& hi, uint32_t& lo) {
    hi = f2tf(v);
    lo = f2tf(v - __uint_as_float(hi));
}
__device__ __forceinline__ void mma8(float c[4], const uint32_t a[4], uint32_t b0, uint32_t b1) {
    asm volatile(
        "mma.sync.aligned.m16n8k8.row.col.f32.tf32.tf32.f32 "
        "{%0,%1,%2,%3}, {%4,%5,%6,%7}, {%8,%9}, {%0,%1,%2,%3};"
        : "+f"(c[0]), "+f"(c[1]), "+f"(c[2]), "+f"(c[3])
        : "r"(a[0]), "r"(a[1]), "r"(a[2]), "r"(a[3]), "r"(b0), "r"(b1));
}

// One K=32 chunk of warp-level 3-pass tf32 MMA.
// As[k][m] (k rel 0..31, m 0..127+pad), Bs[k][n]. Warp tile 64x32 at (wm*64, wn*32).
__device__ __forceinline__ void mma_chunk(const float (*As)[132], const float (*Bs)[132],
                                          int wm, int wn, int lane, float c[4][4][4]) {
    int r  = lane >> 2;
    int cl = lane & 3;
    #pragma unroll
    for (int kc = 0; kc < 32; kc += 8) {
        uint32_t ah[4][4], al[4][4];
        #pragma unroll
        for (int mf = 0; mf < 4; mf++) {
            int rb = wm * 64 + mf * 16;
            float f0 = As[kc + cl][rb + r];
            float f1 = As[kc + cl][rb + r + 8];
            float f2 = As[kc + cl + 4][rb + r];
            float f3 = As[kc + cl + 4][rb + r + 8];
            split_tf(f0, ah[mf][0], al[mf][0]);
            split_tf(f1, ah[mf][1], al[mf][1]);
            split_tf(f2, ah[mf][2], al[mf][2]);
            split_tf(f3, ah[mf][3], al[mf][3]);
        }
        #pragma unroll
        for (int nf = 0; nf < 4; nf++) {
            int cb = wn * 32 + nf * 8;
            float g0 = Bs[kc + cl][cb + r];
            float g1 = Bs[kc + cl + 4][cb + r];
            uint32_t bh0, bl0, bh1, bl1;
            split_tf(g0, bh0, bl0);
            split_tf(g1, bh1, bl1);
            #pragma unroll
            for (int mf = 0; mf < 4; mf++) {
                mma8(c[mf][nf], ah[mf], bh0, bh1);   // hi*hi
                mma8(c[mf][nf], al[mf], bh0, bh1);   // lo*hi
                mma8(c[mf][nf], ah[mf], bl0, bl1);   // hi*lo
            }
        }
    }
}

// ---------------------------------------------------------------------------
// Prep kernels
// ---------------------------------------------------------------------------
__global__ void build_wT_kernel(const float* __restrict__ Wq,
                                const float* __restrict__ Wk,
                                const float* __restrict__ W1,
                                const float* __restrict__ W2) {
    int idx = blockIdx.x * 256 + threadIdx.x;   // over NBLD*256
    int n = idx >> 8;     // output channel 0..1791
    int k = idx & 255;    // input channel
    int b = n >> 8, c = n & 255;
    float v;
    switch (b) {
        case 0: v = Wq[(size_t)k * 256 + c];         break;
        case 1: v = Wq[(size_t)(k + 256) * 256 + c]; break;
        case 2: v = Wk[(size_t)k * 256 + c];         break;
        case 3: v = Wk[(size_t)(k + 256) * 256 + c]; break;
        case 4: v = W1[(size_t)k * 256 + c];         break;
        case 5: v = W1[(size_t)(k + 256) * 256 + c]; break;
        default: v = W2[(size_t)k * 256 + c];        break;
    }
    g_WT[(size_t)n * 256 + k] = v;
}

__global__ void build_bias_kernel(const float* __restrict__ bq,
                                  const float* __restrict__ bk,
                                  const float* __restrict__ b1,
                                  const float* __restrict__ b2) {
    int n = blockIdx.x * 256 + threadIdx.x;
    int b = n >> 8, c = n & 255;
    float v = 0.f;
    if (b == 1) v = bq[c];
    else if (b == 3) v = bk[c];
    else if (b == 4) v = b1[c];
    else if (b == 6) v = b2[c];
    g_bias[n] = v;
}

__global__ void norms_kernel(const float* __restrict__ x) {
    int row  = blockIdx.x * 8 + (threadIdx.x >> 5);
    int lane = threadIdx.x & 31;
    const float4* xr = (const float4*)(x + (size_t)row * 256);
    float s = 0.f;
    #pragma unroll
    for (int r = 0; r < 2; r++) {
        float4 v = xr[lane + 32 * r];
        s += v.x * v.x + v.y * v.y + v.z * v.z + v.w * v.w;
    }
    #pragma unroll
    for (int o = 16; o; o >>= 1) s += __shfl_xor_sync(0xffffffffu, s, o);
    if (lane == 0) g_n2[row] = s;
}

// ---------------------------------------------------------------------------
// Node GEMM: g_NB[m][n] = x[m] . WT[n] + bias[n].  grid (14, 79), 256 thr.
// ---------------------------------------------------------------------------
__global__ void __launch_bounds__(256) node_mma_kernel(const float* __restrict__ x) {
    __shared__ float As[32][132];
    __shared__ float Bs[32][132];

    int t = threadIdx.x, lane = t & 31, wid = t >> 5;
    int wm = wid >> 2, wn = wid & 3;
    int m0 = blockIdx.y * 128, n0 = blockIdx.x * 128;

    float c[4][4][4];
    #pragma unroll
    for (int a = 0; a < 4; a++)
        #pragma unroll
        for (int b = 0; b < 4; b++)
            #pragma unroll
            for (int d = 0; d < 4; d++) c[a][b][d] = 0.f;

    int lr = t >> 1, lk = (t & 1) * 16;
    int arow = (m0 + lr < NN) ? (m0 + lr) : (NN - 1);
    const float* ap = x + (size_t)arow * 256 + lk;
    const float* bp = g_WT + (size_t)(n0 + lr) * 256 + lk;

    for (int k0 = 0; k0 < 256; k0 += 32) {
        #pragma unroll
        for (int j = 0; j < 4; j++) {
            float4 v = *(const float4*)(ap + k0 + 4 * j);
            As[lk + 4 * j + 0][lr] = v.x; As[lk + 4 * j + 1][lr] = v.y;
            As[lk + 4 * j + 2][lr] = v.z; As[lk + 4 * j + 3][lr] = v.w;
            float4 w = *(const float4*)(bp + k0 + 4 * j);
            Bs[lk + 4 * j + 0][lr] = w.x; Bs[lk + 4 * j + 1][lr] = w.y;
            Bs[lk + 4 * j + 2][lr] = w.z; Bs[lk + 4 * j + 3][lr] = w.w;
        }
        __syncthreads();
        mma_chunk(As, Bs, wm, wn, lane, c);
        __syncthreads();
    }

    int r = lane >> 2, q = lane & 3;
    #pragma unroll
    for (int mf = 0; mf < 4; mf++) {
        #pragma unroll
        for (int nf = 0; nf < 4; nf++) {
            int row = m0 + wm * 64 + mf * 16 + r;
            int col = n0 + wn * 32 + nf * 8 + 2 * q;
            float b0 = g_bias[col], b1 = g_bias[col + 1];
            if (row < NN)
                *(float2*)(g_NB + (size_t)row * NBLD + col) =
                    make_float2(c[mf][nf][0] + b0, c[mf][nf][1] + b1);
            if (row + 8 < NN)
                *(float2*)(g_NB + (size_t)(row + 8) * NBLD + col) =
                    make_float2(c[mf][nf][2] + b0, c[mf][nf][3] + b1);
        }
    }
}

// ---------------------------------------------------------------------------
// Gram: G = x @ x^T, upper tiles + mirror.  grid (79, 79), 256 thr.
// ---------------------------------------------------------------------------
__global__ void __launch_bounds__(256) gram_mma_kernel(const float* __restrict__ x) {
    if (blockIdx.x < blockIdx.y) return;
    __shared__ float As[32][132];
    __shared__ float Bs[32][132];

    int t = threadIdx.x, lane = t & 31, wid = t >> 5;
    int wm = wid >> 2, wn = wid & 3;
    int m0 = blockIdx.y * 128, n0 = blockIdx.x * 128;
    bool diag = (blockIdx.x == blockIdx.y);

    float c[4][4][4];
    #pragma unroll
    for (int a = 0; a < 4; a++)
        #pragma unroll
        for (int b = 0; b < 4; b++)
            #pragma unroll
            for (int d = 0; d < 4; d++) c[a][b][d] = 0.f;

    int lr = t >> 1, lk = (t & 1) * 16;
    int arow = (m0 + lr < NN) ? (m0 + lr) : (NN - 1);
    int brow = (n0 + lr < NN) ? (n0 + lr) : (NN - 1);
    const float* ap = x + (size_t)arow * 256 + lk;
    const float* bp = x + (size_t)brow * 256 + lk;

    for (int k0 = 0; k0 < 256; k0 += 32) {
        #pragma unroll
        for (int j = 0; j < 4; j++) {
            float4 v = *(const float4*)(ap + k0 + 4 * j);
            As[lk + 4 * j + 0][lr] = v.x; As[lk + 4 * j + 1][lr] = v.y;
            As[lk + 4 * j + 2][lr] = v.z; As[lk + 4 * j + 3][lr] = v.w;
            float4 w = *(const float4*)(bp + k0 + 4 * j);
            Bs[lk + 4 * j + 0][lr] = w.x; Bs[lk + 4 * j + 1][lr] = w.y;
            Bs[lk + 4 * j + 2][lr] = w.z; Bs[lk + 4 * j + 3][lr] = w.w;
        }
        __syncthreads();
        mma_chunk(As, Bs, wm, wn, lane, c);
        __syncthreads();
    }

    int r = lane >> 2, q = lane & 3;
    // direct store (upper tile)
    #pragma unroll
    for (int mf = 0; mf < 4; mf++) {
        #pragma unroll
        for (int nf = 0; nf < 4; nf++) {
            int row = m0 + wm * 64 + mf * 16 + r;
            int col = n0 + wn * 32 + nf * 8 + 2 * q;
            if (col + 1 < NN) {
                if (row < NN)
                    *(float2*)(g_G + (size_t)row * LDGG + col) =
                        make_float2(c[mf][nf][0], c[mf][nf][1]);
                if (row + 8 < NN)
                    *(float2*)(g_G + (size_t)(row + 8) * LDGG + col) =
                        make_float2(c[mf][nf][2], c[mf][nf][3]);
            } else if (col < NN) {
                if (row < NN)     g_G[(size_t)row * LDGG + col]       = c[mf][nf][0];
                if (row + 8 < NN) g_G[(size_t)(row + 8) * LDGG + col] = c[mf][nf][2];
            }
        }
    }

    // mirror store (off-diag).  m range always < NN here (m0 <= 9856).
    if (!diag) {
        // staging area: reuse As (rows 0..31) and Bs (rows 32..63): sT[n_local][m_local]
        for (int h = 0; h < 2; h++) {       // column halves of the tile
            __syncthreads();
            if ((wn >> 1) == h) {
                #pragma unroll
                for (int mf = 0; mf < 4; mf++) {
                    #pragma unroll
                    for (int nf = 0; nf < 4; nf++) {
                        int rowl = wm * 64 + mf * 16 + r;
                        int cn   = (wn & 1) * 32 + nf * 8 + 2 * q;   // 0..63
                        float* s0 = (cn < 32) ? As[cn] : Bs[cn - 32];
                        float* s1 = (cn + 1 < 32) ? As[cn + 1] : Bs[cn + 1 - 32];
                        s0[rowl] = c[mf][nf][0];
                        s1[rowl] = c[mf][nf][1];
                        s0[rowl + 8] = c[mf][nf][2];
                        s1[rowl + 8] = c[mf][nf][3];
                    }
                }
            }
            __syncthreads();
            int n    = t >> 2;         // 0..63
            int part = t & 3;          // 32 floats each
            int gn = n0 + h * 64 + n;
            if (gn < NN) {
                const float* src = (n < 32) ? As[n] : Bs[n - 32];
                float* dst = g_G + (size_t)gn * LDGG + m0 + part * 32;
                #pragma unroll
                for (int j = 0; j < 8; j++)
                    *(float4*)(dst + 4 * j) = *(const float4*)(src + part * 32 + 4 * j);
            }
        }
    }
}

// ---------------------------------------------------------------------------
// Edge GEMM (fused relu(P_i+R_j)): g_U[e] = relu(P_i+R_j) . W2T[n]
// grid (2, 1250), 256 thr.
// ---------------------------------------------------------------------------
__global__ void __launch_bounds__(256) edge_mma_kernel() {
    __shared__ float As[32][132];
    __shared__ float Bs[32][132];

    int t = threadIdx.x, lane = t & 31, wid = t >> 5;
    int wm = wid >> 2, wn = wid & 3;
    int m0 = blockIdx.y * 128, n0 = blockIdx.x * 128;

    float c[4][4][4];
    #pragma unroll
    for (int a = 0; a < 4; a++)
        #pragma unroll
        for (int b = 0; b < 4; b++)
            #pragma unroll
            for (int d = 0; d < 4; d++) c[a][b][d] = 0.f;

    int lr = t >> 1, lk = (t & 1) * 16;
    int e = m0 + lr;
    int inode = e >> 4;
    int jnode = g_nbr[e];
    const float* pp = g_NB + (size_t)inode * NBLD + 1024 + lk;    // P (+b1)
    const float* rp = g_NB + (size_t)jnode * NBLD + 1280 + lk;    // R
    const float* bp = g_WT + (size_t)(1536 + n0 + lr) * 256 + lk; // W2T

    for (int k0 = 0; k0 < 256; k0 += 32) {
        #pragma unroll
        for (int j = 0; j < 4; j++) {
            float4 pv = *(const float4*)(pp + k0 + 4 * j);
            float4 rv = *(const float4*)(rp + k0 + 4 * j);
            As[lk + 4 * j + 0][lr] = fmaxf(pv.x + rv.x, 0.f);
            As[lk + 4 * j + 1][lr] = fmaxf(pv.y + rv.y, 0.f);
            As[lk + 4 * j + 2][lr] = fmaxf(pv.z + rv.z, 0.f);
            As[lk + 4 * j + 3][lr] = fmaxf(pv.w + rv.w, 0.f);
            float4 w = *(const float4*)(bp + k0 + 4 * j);
            Bs[lk + 4 * j + 0][lr] = w.x; Bs[lk + 4 * j + 1][lr] = w.y;
            Bs[lk + 4 * j + 2][lr] = w.z; Bs[lk + 4 * j + 3][lr] = w.w;
        }
        __syncthreads();
        mma_chunk(As, Bs, wm, wn, lane, c);
        __syncthreads();
    }

    int r = lane >> 2, q = lane & 3;
    #pragma unroll
    for (int mf = 0; mf < 4; mf++) {
        #pragma unroll
        for (int nf = 0; nf < 4; nf++) {
            int row = m0 + wm * 64 + mf * 16 + r;
            int col = n0 + wn * 32 + nf * 8 + 2 * q;
            *(float2*)(g_U + (size_t)row * 256 + col) =
                make_float2(c[mf][nf][0], c[mf][nf][1]);
            *(float2*)(g_U + (size_t)(row + 8) * 256 + col) =
                make_float2(c[mf][nf][2], c[mf][nf][3]);
        }
    }
}

// ---------------------------------------------------------------------------
// Top-16 nearest per row (1 warp per row)
// ---------------------------------------------------------------------------
__global__ void topk_kernel() {
    __shared__ float sd[8][512];
    __shared__ int   si[8][512];

    int w    = threadIdx.x >> 5;
    int lane = threadIdx.x & 31;
    int row  = blockIdx.x * 8 + w;

    const float FINF = __int_as_float(0x7f800000);
    float n2i = g_n2[row];
    const float* Gr = g_G + (size_t)row * LDGG;

    float best[16];
    int   bid[16];
    #pragma unroll
    for (int q = 0; q < 16; q++) { best[q] = FINF; bid[q] = -1; }
    float worst = FINF;

    for (int j = lane; j < NN; j += 32) {
        float d = n2i + g_n2[j] - 2.f * Gr[j];
        if (j == row) d = FINF;
        if (d < worst) {
            float mx = best[0]; int am = 0;
            #pragma unroll
            for (int q = 1; q < 16; q++) if (best[q] > mx) { mx = best[q]; am = q; }
            #pragma unroll
            for (int q = 0; q < 16; q++) if (q == am) { best[q] = d; bid[q] = j; }
            worst = best[0];
            #pragma unroll
            for (int q = 1; q < 16; q++) worst = fmaxf(worst, best[q]);
        }
    }

    #pragma unroll
    for (int q = 0; q < 16; q++) {
        sd[w][lane * 16 + q] = best[q];
        si[w][lane * 16 + q] = bid[q];
    }
    __syncwarp();

    for (int sel = 0; sel < 16; sel++) {
        float m = FINF; int mp = 0;
        #pragma unroll
        for (int r2 = 0; r2 < 16; r2++) {
            int p = lane + 32 * r2;
            float v = sd[w][p];
            if (v < m) { m = v; mp = p; }
        }
        #pragma unroll
        for (int o = 16; o; o >>= 1) {
            float om = __shfl_xor_sync(0xffffffffu, m, o);
            int   op = __shfl_xor_sync(0xffffffffu, mp, o);
            if (om < m) { m = om; mp = op; }
        }
        if (lane == 0) {
            g_nbr[row * 16 + sel] = si[w][mp];
            sd[w][mp] = FINF;
        }
        __syncwarp();
    }
}

// ---------------------------------------------------------------------------
// Combine: ew per edge + mixing + mean aggregation (biases already folded)
// ---------------------------------------------------------------------------
__global__ void combine_kernel(float* __restrict__ out) {
    int i = blockIdx.x;
    int t = threadIdx.x;         // 0..127
    __shared__ float qb[256], kb[256], sb[256], ewsh[4];

    const float* nbi = g_NB + (size_t)i * NBLD;
    for (int c = t; c < 256; c += 128) {
        qb[c] = nbi[256 + c];
        kb[c] = nbi[768 + c];
        sb[c] = nbi[1536 + c];
    }
    __syncthreads();

    int w    = t >> 5;
    int lane = t & 31;
    int h = w >> 1, g = w & 1;

    float a0 = 0.f, a1 = 0.f;

    for (int kk = 0; kk < 16; kk++) {
        int e = i * 16 + kk;
        int j = g_nbr[e];
        const float* qaj = g_NB + (size_t)j * NBLD;
        const float* kaj = qaj + 512;
        float s = 0.f;
        #pragma unroll
        for (int r = 0; r < 4; r++) {
            int d = lane + 32 * r;
            float qv = qaj[h * 128 + d] + qb[h * 128 + d];
            float kv = kaj[g * 128 + d] + kb[g * 128 + d];
            s = fmaf(qv, kv, s);
        }
        #pragma unroll
        for (int o = 16; o; o >>= 1) s += __shfl_xor_sync(0xffffffffu, s, o);
        if (lane == 0) ewsh[w] = s * 0.0625f;
        __syncthreads();
        float e00 = ewsh[0], e01 = ewsh[1], e10 = ewsh[2], e11 = ewsh[3];
        float2 u2 = *(const float2*)&g_U[(size_t)e * 256 + 2 * t];
        float u0 = u2.x + sb[2 * t];
        float u1 = u2.y + sb[2 * t + 1];
        a0 += u0 * e00 + u1 * e10;
        a1 += u0 * e01 + u1 * e11;
        __syncthreads();
    }

    out[(size_t)i * 256 + 2 * t]     = a0 * 0.0625f;
    out[(size_t)i * 256 + 2 * t + 1] = a1 * 0.0625f;
}

// ---------------------------------------------------------------------------
// Launch
// ---------------------------------------------------------------------------
extern "C" void kernel_launch(void* const* d_in, const int* in_sizes, int n_in,
                              void* d_out, int out_size) {
    const float* x  = (const float*)d_in[0];
    const float* W1 = (const float*)d_in[1];
    const float* b1 = (const float*)d_in[2];
    const float* W2 = (const float*)d_in[3];
    const float* b2 = (const float*)d_in[4];
    const float* Wq = (const float*)d_in[5];
    const float* bq = (const float*)d_in[6];
    const float* Wk = (const float*)d_in[7];
    const float* bk = (const float*)d_in[8];
    float* out = (float*)d_out;

    build_wT_kernel<<<NBLD, 256>>>(Wq, Wk, W1, W2);
    build_bias_kernel<<<7, 256>>>(bq, bk, b1, b2);
    norms_kernel<<<1250, 256>>>(x);

    node_mma_kernel<<<dim3(14, 79), 256>>>(x);
    gram_mma_kernel<<<dim3(79, 79), 256>>>(x);
    topk_kernel<<<1250, 256>>>();
    edge_mma_kernel<<<dim3(2, 1250), 256>>>();
    combine_kernel<<<NN, 128>>>(out);
}